// round 16
// baseline (speedup 1.0000x reference)
#include <cuda_runtime.h>
#include <cuda_fp16.h>

#define NN    100000
#define EMAX  1700000
#define INC   128
#define H1DIM 64
#define HEADS 8
#define HID   8
#define OUTC  40
#define FULL  0xffffffffu
#define SCANB 98            // ceil(NN/1024)

// ---- scratch ----
__device__ __half g_h1h[NN * H1DIM];   // layer-1 features, fp16 (gather payload)
__device__ float  g_as1[NN * HEADS];
__device__ float  g_ad1[NN * HEADS];
__device__ __half g_h2h[NN * OUTC];    // layer-2 features, fp16 (gather payload)
__device__ float  g_as2[NN];
__device__ float  g_ad2[NN];
__device__ int    g_cnt[NN];
__device__ int    g_cur[NN];
__device__ int    g_rowptr[NN + 1];
__device__ int    g_blocksum[SCANB];
__device__ int    g_csr_src[EMAX];
__device__ unsigned g_sync;            // monotonic grid-barrier counter

// ---- histogram of destinations (g_cnt/g_cur zeroed by memset nodes) ----
__global__ void __launch_bounds__(256) k_hist(const int* __restrict__ dst, int nE) {
    int e = blockIdx.x * blockDim.x + threadIdx.x;
    if (e < nE) atomicAdd(&g_cnt[dst[e]], 1);
}

// generation-based grid barrier (R8-validated): 98 blocks all co-resident.
__device__ __forceinline__ void gsync() {
    __syncthreads();
    __threadfence();
    if (threadIdx.x == 0) {
        unsigned my = atomicAdd(&g_sync, 1u);
        unsigned target = (my / SCANB + 1u) * SCANB;
        while (atomicAdd(&g_sync, 0u) < target) { }
    }
    __syncthreads();
}

// ---- fused scan + CSR fill (one launch, 98 co-resident blocks) ----
__global__ void __launch_bounds__(1024) k_scanfill(const int* __restrict__ src,
                                                   const int* __restrict__ dst, int nE) {
    __shared__ int sm[1024];
    __shared__ int bs[128];
    const int t = threadIdx.x;
    const int b = blockIdx.x;
    const int i = b * 1024 + t;

    int v = (i < NN) ? g_cnt[i] : 0;
    sm[t] = v;
    __syncthreads();
    for (int d = 1; d < 1024; d <<= 1) {
        int u = (t >= d) ? sm[t - d] : 0;
        __syncthreads();
        sm[t] += u;
        __syncthreads();
    }
    if (t == 1023) g_blocksum[b] = sm[1023];

    gsync();

    if (t < 128) bs[t] = (t < SCANB) ? g_blocksum[t] : 0;
    __syncthreads();
    for (int d = 1; d < 128; d <<= 1) {
        int u = (t >= d && t < 128) ? bs[t - d] : 0;
        __syncthreads();
        if (t < 128) bs[t] += u;
        __syncthreads();
    }
    int boff = (b == 0) ? 0 : bs[b - 1];
    if (i < NN) g_rowptr[i] = boff + sm[t] - v;          // exclusive prefix
    if (b == SCANB - 1 && t == 1023) g_rowptr[NN] = bs[SCANB - 1];

    gsync();

    for (int e = b * 1024 + t; e < nE; e += SCANB * 1024) {
        int d = dst[e];
        int p = g_rowptr[d] + atomicAdd(&g_cur[d], 1);
        g_csr_src[p] = src[e];
    }
}

// ---- layer-1 GEMM + attention dots; features stored as fp16 ----
__global__ void __launch_bounds__(256) k_gemm1(
        const float* __restrict__ x,  const float* __restrict__ W1,
        const float* __restrict__ as_w, const float* __restrict__ ad_w) {
    __shared__ float wT[INC * H1DIM];
    __shared__ float xs[16 * INC];
    const int t = threadIdx.x;
    const int nb = blockIdx.x * 16;

    for (int i = t; i < H1DIM * INC; i += 256) {
        int f = i >> 7, k = i & 127;
        wT[k * H1DIM + f] = W1[i];
    }
    for (int i = t; i < 16 * INC; i += 256) {
        int node = nb + (i >> 7);
        xs[i] = x[node * INC + (i & 127)];
    }
    __syncthreads();

    const int f = t & 63;
    const int g = t >> 6;
    float acc[4] = {0.f, 0.f, 0.f, 0.f};

    const float4* xr0 = (const float4*)(xs + (g +  0) * INC);
    const float4* xr1 = (const float4*)(xs + (g +  4) * INC);
    const float4* xr2 = (const float4*)(xs + (g +  8) * INC);
    const float4* xr3 = (const float4*)(xs + (g + 12) * INC);

    #pragma unroll 4
    for (int k4 = 0; k4 < INC / 4; k4++) {
        int kb = k4 * 4;
        float w0 = wT[(kb + 0) * H1DIM + f];
        float w1 = wT[(kb + 1) * H1DIM + f];
        float w2 = wT[(kb + 2) * H1DIM + f];
        float w3 = wT[(kb + 3) * H1DIM + f];
        float4 v;
        v = xr0[k4]; acc[0] += v.x*w0 + v.y*w1 + v.z*w2 + v.w*w3;
        v = xr1[k4]; acc[1] += v.x*w0 + v.y*w1 + v.z*w2 + v.w*w3;
        v = xr2[k4]; acc[2] += v.x*w0 + v.y*w1 + v.z*w2 + v.w*w3;
        v = xr3[k4]; acc[3] += v.x*w0 + v.y*w1 + v.z*w2 + v.w*w3;
    }

    float aw = as_w[f], dw = ad_w[f];
    #pragma unroll
    for (int i = 0; i < 4; i++) {
        int node = nb + g + 4 * i;
        float vs = acc[i] * aw, vd = acc[i] * dw;
        #pragma unroll
        for (int off = 1; off < HID; off <<= 1) {
            vs += __shfl_xor_sync(FULL, vs, off);
            vd += __shfl_xor_sync(FULL, vd, off);
        }
        g_h1h[node * H1DIM + f] = __float2half(acc[i]);   // fp16 payload
        if ((f & 7) == 0) {
            g_as1[node * HEADS + (f >> 3)] = vs;          // logits stay fp32
            g_ad1[node * HEADS + (f >> 3)] = vd;
        }
    }
}

// ---- FUSED layer-1 aggregation + layer-2 GEMM + att2 dots ----
// feature gather: lane l loads half2 (channels 2l,2l+1) -> 128B = 1 line/edge
__global__ void __launch_bounds__(320) k_agg1g2(const float* __restrict__ b1,
                                                const float* __restrict__ W2,
                                                const float* __restrict__ as_w,
                                                const float* __restrict__ ad_w) {
    __shared__ float wT[H1DIM * OUTC];             // 10KB
    __shared__ __align__(16) float sact[8][H1DIM]; // 2KB
    __shared__ float ps[8 * OUTC];
    __shared__ float pd[8 * OUTC];
    const int t   = threadIdx.x;
    const int wid = t >> 5;
    const int l   = t & 31;
    const int nb  = blockIdx.x * 8;

    if (wid >= 8) {
        for (int i = t - 256; i < OUTC * H1DIM; i += 64) {
            int f = i >> 6, k = i & 63;
            wT[k * OUTC + f] = W2[i];
        }
    } else {
        const int n = nb + wid;
        const int start = g_rowptr[n], end = g_rowptr[n + 1];

        const int g  = l >> 3;
        const int h  = l & 7;
        const int hl = l >> 2;
        const float adh = g_ad1[n * HEADS + h];
        const __half2* __restrict__ H = (const __half2*)g_h1h;  // 32 half2/row

        int m = end - start; if (m > 4) m = 4;
        int s = 0; float v = 0.f;
        if (g < m) {
            s = g_csr_src[start + g];
            v = g_as1[s * HEADS + h] + adh;
        }

        float accx = 0.f, accy = 0.f, den = 0.f;
        for (int eb = start; eb < end; eb += 4) {
            int ebn = eb + 4;
            int mn = end - ebn; if (mn > 4) mn = 4;
            int sn = 0; float vn = 0.f;
            if (g < mn) {
                sn = g_csr_src[ebn + g];
                vn = g_as1[sn * HEADS + h] + adh;
            }

            float lv = (v > 0.f) ? v : 0.2f * v;
            float ex = (g < m) ? __expf(lv) : 0.f;
            den += ex;

            int s0 = __shfl_sync(FULL, s, 0);
            int s1 = __shfl_sync(FULL, s, 8);
            int s2 = __shfl_sync(FULL, s, 16);
            int s3 = __shfl_sync(FULL, s, 24);
            float x0 = __shfl_sync(FULL, ex, hl);
            float x1 = __shfl_sync(FULL, ex, 8 + hl);
            float x2 = __shfl_sync(FULL, ex, 16 + hl);
            float x3 = __shfl_sync(FULL, ex, 24 + hl);

            float2 r0 = __half22float2(H[s0 * 32 + l]);
            float2 r1 = __half22float2(H[s1 * 32 + l]);
            float2 r2 = __half22float2(H[s2 * 32 + l]);
            float2 r3 = __half22float2(H[s3 * 32 + l]);

            accx += x0*r0.x + x1*r1.x + x2*r2.x + x3*r3.x;
            accy += x0*r0.y + x1*r1.y + x2*r2.y + x3*r3.y;

            m = mn; s = sn; v = vn;
        }
        den += __shfl_xor_sync(FULL, den, 8);
        den += __shfl_xor_sync(FULL, den, 16);
        float dd = __shfl_sync(FULL, den, hl);

        float2 bb = ((const float2*)b1)[l];
        float o0 = accx / dd + bb.x;
        float o1 = accy / dd + bb.y;
        float2 r;
        r.x = (o0 > 0.f) ? o0 : expm1f(o0);
        r.y = (o1 > 0.f) ? o1 : expm1f(o1);
        ((float2*)sact[wid])[l] = r;
    }
    __syncthreads();

    // gemm2 phase from smem act (fp32); h2 stored fp16
    const int f = t % OUTC;
    const int local = t / OUTC;
    const float4* ar = (const float4*)(sact[local]);
    float acc = 0.f;
    #pragma unroll 4
    for (int k4 = 0; k4 < H1DIM / 4; k4++) {
        int kb = k4 * 4;
        float4 vv = ar[k4];
        acc += vv.x * wT[(kb + 0) * OUTC + f];
        acc += vv.y * wT[(kb + 1) * OUTC + f];
        acc += vv.z * wT[(kb + 2) * OUTC + f];
        acc += vv.w * wT[(kb + 3) * OUTC + f];
    }
    g_h2h[(nb + local) * OUTC + f] = __float2half(acc);
    ps[local * OUTC + f] = acc * as_w[f];
    pd[local * OUTC + f] = acc * ad_w[f];
    __syncthreads();

    if (t < 16) {
        int node = t & 7;
        const float* p = (t < 8) ? (ps + node * OUTC) : (pd + node * OUTC);
        float ss = 0.f;
        #pragma unroll
        for (int i = 0; i < OUTC; i++) ss += p[i];
        if (t < 8) g_as2[nb + node] = ss;
        else       g_ad2[nb + node] = ss;
    }
}

// ---- layer-2 aggregation: warp/node, half2 lanes (l<20) ----
__global__ void __launch_bounds__(256, 5) k_agg2(const float* __restrict__ b2,
                                                 float* __restrict__ out) {
    const int n = blockIdx.x * 8 + (threadIdx.x >> 5);
    const int l = threadIdx.x & 31;
    const int start = g_rowptr[n], end = g_rowptr[n + 1];
    const float ad = __ldg(&g_ad2[n]);
    const __half2* __restrict__ H = (const __half2*)g_h2h;   // 20 half2/row
    const bool act = (l < 20);
    const float2 zz = make_float2(0.f, 0.f);

    float accx = 0.f, accy = 0.f, den = 0.f;
    for (int eb = start; eb < end; eb += 32) {
        int m = end - eb; if (m > 32) m = 32;
        int s = 0; float ex = 0.f;
        if (l < m) {
            s = __ldg(&g_csr_src[eb + l]);
            float v = __ldg(&g_as2[s]) + ad;
            v = (v > 0.f) ? v : 0.2f * v;
            ex = __expf(v);
        }
        den += ex;
        #pragma unroll
        for (int j = 0; j < 32; j += 4) {
            if (j >= m) break;
            int   s0 = __shfl_sync(FULL, s,  j + 0);
            int   s1 = __shfl_sync(FULL, s,  j + 1);
            int   s2 = __shfl_sync(FULL, s,  j + 2);
            int   s3 = __shfl_sync(FULL, s,  j + 3);
            float x0 = __shfl_sync(FULL, ex, j + 0);
            float x1 = __shfl_sync(FULL, ex, j + 1);
            float x2 = __shfl_sync(FULL, ex, j + 2);
            float x3 = __shfl_sync(FULL, ex, j + 3);
            float2 r0 = act ? __half22float2(__ldg(&H[s0 * 20 + l])) : zz;
            float2 r1 = act ? __half22float2(__ldg(&H[s1 * 20 + l])) : zz;
            float2 r2 = act ? __half22float2(__ldg(&H[s2 * 20 + l])) : zz;
            float2 r3 = act ? __half22float2(__ldg(&H[s3 * 20 + l])) : zz;
            accx += x0 * r0.x + x1 * r1.x + x2 * r2.x + x3 * r3.x;
            accy += x0 * r0.y + x1 * r1.y + x2 * r2.y + x3 * r3.y;
        }
    }
    #pragma unroll
    for (int off = 1; off < 32; off <<= 1) den += __shfl_xor_sync(FULL, den, off);

    if (act) {
        float2 bb = __ldg(&((const float2*)b2)[l]);
        float2 r;
        r.x = accx / den + bb.x;
        r.y = accy / den + bb.y;
        ((float2*)out)[n * 20 + l] = r;
    }
}

extern "C" void kernel_launch(void* const* d_in, const int* in_sizes, int n_in,
                              void* d_out, int out_size) {
    const float* x   = (const float*)d_in[0];
    const int*   ei  = (const int*)  d_in[1];
    const float* W1  = (const float*)d_in[2];
    const float* as1 = (const float*)d_in[3];
    const float* ad1 = (const float*)d_in[4];
    const float* b1  = (const float*)d_in[5];
    const float* W2  = (const float*)d_in[6];
    const float* as2 = (const float*)d_in[7];
    const float* ad2 = (const float*)d_in[8];
    const float* b2  = (const float*)d_in[9];
    float* out = (float*)d_out;

    int nE = in_sizes[1] / 2;
    const int* src = ei;
    const int* dst = ei + nE;

    const int T = 256;
    int eg = (nE + T - 1) / T;

    static cudaStream_t s2 = nullptr;
    static cudaEvent_t evFork = nullptr, evJoin = nullptr;
    static int* cnt_addr = nullptr;
    static int* cur_addr = nullptr;
    if (s2 == nullptr) {
        cudaStreamCreateWithFlags(&s2, cudaStreamNonBlocking);
        cudaEventCreateWithFlags(&evFork, cudaEventDisableTiming);
        cudaEventCreateWithFlags(&evJoin, cudaEventDisableTiming);
        cudaGetSymbolAddress((void**)&cnt_addr, g_cnt);
        cudaGetSymbolAddress((void**)&cur_addr, g_cur);
    }

    // fork first; gemm1 submitted (and recorded) BEFORE any wait on evJoin
    cudaEventRecord(evFork, 0);
    cudaStreamWaitEvent(s2, evFork, 0);
    k_gemm1<<<NN / 16, 256, 0, s2>>>(x, W1, as1, ad1);   // launch #1 (s2)
    cudaEventRecord(evJoin, s2);

    // main stream: CSR build
    cudaMemsetAsync(cnt_addr, 0, NN * sizeof(int), 0);
    cudaMemsetAsync(cur_addr, 0, NN * sizeof(int), 0);
    k_hist    <<<eg, T>>>(dst, nE);            // launch #2
    k_scanfill<<<SCANB, 1024>>>(src, dst, nE); // launch #3

    // join: agg1g2 needs gemm1 results
    cudaStreamWaitEvent(0, evJoin, 0);
    k_agg1g2<<<NN / 8, 320>>>(b1, W2, as2, ad2);   // launch #4 -> ncu capture
    k_agg2  <<<NN / 8, 256>>>(b2, out);            // launch #5
}

// round 17
// speedup vs baseline: 1.0752x; 1.0752x over previous
#include <cuda_runtime.h>
#include <cuda_fp16.h>

#define NN    100000
#define EMAX  1700000
#define INC   128
#define H1DIM 64
#define HEADS 8
#define HID   8
#define OUTC  40
#define FULL  0xffffffffu
#define SCANB 98            // ceil(NN/1024)

// ---- scratch ----
__device__ __half g_h1h[NN * H1DIM];   // layer-1 features, fp16 (gather payload)
__device__ float  g_as1[NN * HEADS];
__device__ float  g_ad1[NN * HEADS];
__device__ __half g_h2h[NN * OUTC];    // layer-2 features, fp16 (gather payload)
__device__ float  g_as2[NN];
__device__ float  g_ad2[NN];
__device__ int    g_cnt[NN];
__device__ int    g_cur[NN];
__device__ int    g_rowptr[NN + 1];
__device__ int    g_blocksum[SCANB];
__device__ int    g_csr_src[EMAX];
__device__ unsigned g_sync;            // monotonic grid-barrier counter

// ---- histogram of destinations (g_cnt/g_cur zeroed by memset nodes) ----
__global__ void __launch_bounds__(256) k_hist(const int* __restrict__ dst, int nE) {
    int e = blockIdx.x * blockDim.x + threadIdx.x;
    if (e < nE) atomicAdd(&g_cnt[dst[e]], 1);
}

// generation-based grid barrier (R8-validated): 98 blocks all co-resident.
__device__ __forceinline__ void gsync() {
    __syncthreads();
    __threadfence();
    if (threadIdx.x == 0) {
        unsigned my = atomicAdd(&g_sync, 1u);
        unsigned target = (my / SCANB + 1u) * SCANB;
        while (atomicAdd(&g_sync, 0u) < target) { }
    }
    __syncthreads();
}

// ---- fused scan + CSR fill (one launch, 98 co-resident blocks) ----
__global__ void __launch_bounds__(1024) k_scanfill(const int* __restrict__ src,
                                                   const int* __restrict__ dst, int nE) {
    __shared__ int sm[1024];
    __shared__ int bs[128];
    const int t = threadIdx.x;
    const int b = blockIdx.x;
    const int i = b * 1024 + t;

    int v = (i < NN) ? g_cnt[i] : 0;
    sm[t] = v;
    __syncthreads();
    for (int d = 1; d < 1024; d <<= 1) {
        int u = (t >= d) ? sm[t - d] : 0;
        __syncthreads();
        sm[t] += u;
        __syncthreads();
    }
    if (t == 1023) g_blocksum[b] = sm[1023];

    gsync();

    if (t < 128) bs[t] = (t < SCANB) ? g_blocksum[t] : 0;
    __syncthreads();
    for (int d = 1; d < 128; d <<= 1) {
        int u = (t >= d && t < 128) ? bs[t - d] : 0;
        __syncthreads();
        if (t < 128) bs[t] += u;
        __syncthreads();
    }
    int boff = (b == 0) ? 0 : bs[b - 1];
    if (i < NN) g_rowptr[i] = boff + sm[t] - v;          // exclusive prefix
    if (b == SCANB - 1 && t == 1023) g_rowptr[NN] = bs[SCANB - 1];

    gsync();

    for (int e = b * 1024 + t; e < nE; e += SCANB * 1024) {
        int d = dst[e];
        int p = g_rowptr[d] + atomicAdd(&g_cur[d], 1);
        g_csr_src[p] = src[e];
    }
}

// ---- layer-1 GEMM + attention dots; features stored as fp16 ----
__global__ void __launch_bounds__(256) k_gemm1(
        const float* __restrict__ x,  const float* __restrict__ W1,
        const float* __restrict__ as_w, const float* __restrict__ ad_w) {
    __shared__ float wT[INC * H1DIM];
    __shared__ float xs[16 * INC];
    const int t = threadIdx.x;
    const int nb = blockIdx.x * 16;

    for (int i = t; i < H1DIM * INC; i += 256) {
        int f = i >> 7, k = i & 127;
        wT[k * H1DIM + f] = W1[i];
    }
    for (int i = t; i < 16 * INC; i += 256) {
        int node = nb + (i >> 7);
        xs[i] = x[node * INC + (i & 127)];
    }
    __syncthreads();

    const int f = t & 63;
    const int g = t >> 6;
    float acc[4] = {0.f, 0.f, 0.f, 0.f};

    const float4* xr0 = (const float4*)(xs + (g +  0) * INC);
    const float4* xr1 = (const float4*)(xs + (g +  4) * INC);
    const float4* xr2 = (const float4*)(xs + (g +  8) * INC);
    const float4* xr3 = (const float4*)(xs + (g + 12) * INC);

    #pragma unroll 4
    for (int k4 = 0; k4 < INC / 4; k4++) {
        int kb = k4 * 4;
        float w0 = wT[(kb + 0) * H1DIM + f];
        float w1 = wT[(kb + 1) * H1DIM + f];
        float w2 = wT[(kb + 2) * H1DIM + f];
        float w3 = wT[(kb + 3) * H1DIM + f];
        float4 v;
        v = xr0[k4]; acc[0] += v.x*w0 + v.y*w1 + v.z*w2 + v.w*w3;
        v = xr1[k4]; acc[1] += v.x*w0 + v.y*w1 + v.z*w2 + v.w*w3;
        v = xr2[k4]; acc[2] += v.x*w0 + v.y*w1 + v.z*w2 + v.w*w3;
        v = xr3[k4]; acc[3] += v.x*w0 + v.y*w1 + v.z*w2 + v.w*w3;
    }

    float aw = as_w[f], dw = ad_w[f];
    #pragma unroll
    for (int i = 0; i < 4; i++) {
        int node = nb + g + 4 * i;
        float vs = acc[i] * aw, vd = acc[i] * dw;
        #pragma unroll
        for (int off = 1; off < HID; off <<= 1) {
            vs += __shfl_xor_sync(FULL, vs, off);
            vd += __shfl_xor_sync(FULL, vd, off);
        }
        g_h1h[node * H1DIM + f] = __float2half(acc[i]);
        if ((f & 7) == 0) {
            g_as1[node * HEADS + (f >> 3)] = vs;
            g_ad1[node * HEADS + (f >> 3)] = vd;
        }
    }
}

// ---- FUSED layer-1 aggregation + layer-2 GEMM + att2 dots ----
// 512 threads, 16 nodes/block. All threads stage wT first (covered by the
// post-agg barrier); warps 0-15 aggregate; gemm2 uses 320 threads x 2 nodes.
__global__ void __launch_bounds__(512) k_agg1g2(const float* __restrict__ b1,
                                                const float* __restrict__ W2,
                                                const float* __restrict__ as_w,
                                                const float* __restrict__ ad_w) {
    __shared__ float wT[H1DIM * OUTC];              // 10KB
    __shared__ __align__(16) float sact[16][H1DIM]; // 4KB
    __shared__ float ps[16 * OUTC];                 // 2.5KB
    __shared__ float pd[16 * OUTC];                 // 2.5KB
    const int t   = threadIdx.x;
    const int wid = t >> 5;
    const int l   = t & 31;
    const int nb  = blockIdx.x * 16;

    // stage W2^T (no wait here; post-agg __syncthreads orders it before use)
    for (int i = t; i < OUTC * H1DIM; i += 512) {
        int f = i >> 6, k = i & 63;
        wT[k * OUTC + f] = W2[i];
    }

    {   // ---- agg phase: warp per node (R6 body, fp16 gather) ----
        const int n = nb + wid;
        const int start = g_rowptr[n], end = g_rowptr[n + 1];

        const int g  = l >> 3;
        const int h  = l & 7;
        const int hl = l >> 2;
        const float adh = g_ad1[n * HEADS + h];
        const __half2* __restrict__ H = (const __half2*)g_h1h;

        int m = end - start; if (m > 4) m = 4;
        int s = 0; float v = 0.f;
        if (g < m) {
            s = g_csr_src[start + g];
            v = g_as1[s * HEADS + h] + adh;
        }

        float accx = 0.f, accy = 0.f, den = 0.f;
        for (int eb = start; eb < end; eb += 4) {
            int ebn = eb + 4;
            int mn = end - ebn; if (mn > 4) mn = 4;
            int sn = 0; float vn = 0.f;
            if (g < mn) {
                sn = g_csr_src[ebn + g];
                vn = g_as1[sn * HEADS + h] + adh;
            }

            float lv = (v > 0.f) ? v : 0.2f * v;
            float ex = (g < m) ? __expf(lv) : 0.f;
            den += ex;

            int s0 = __shfl_sync(FULL, s, 0);
            int s1 = __shfl_sync(FULL, s, 8);
            int s2 = __shfl_sync(FULL, s, 16);
            int s3 = __shfl_sync(FULL, s, 24);
            float x0 = __shfl_sync(FULL, ex, hl);
            float x1 = __shfl_sync(FULL, ex, 8 + hl);
            float x2 = __shfl_sync(FULL, ex, 16 + hl);
            float x3 = __shfl_sync(FULL, ex, 24 + hl);

            float2 r0 = __half22float2(H[s0 * 32 + l]);
            float2 r1 = __half22float2(H[s1 * 32 + l]);
            float2 r2 = __half22float2(H[s2 * 32 + l]);
            float2 r3 = __half22float2(H[s3 * 32 + l]);

            accx += x0*r0.x + x1*r1.x + x2*r2.x + x3*r3.x;
            accy += x0*r0.y + x1*r1.y + x2*r2.y + x3*r3.y;

            m = mn; s = sn; v = vn;
        }
        den += __shfl_xor_sync(FULL, den, 8);
        den += __shfl_xor_sync(FULL, den, 16);
        float dd = __shfl_sync(FULL, den, hl);

        float2 bb = ((const float2*)b1)[l];
        float o0 = accx / dd + bb.x;
        float o1 = accy / dd + bb.y;
        float2 r;
        r.x = (o0 > 0.f) ? o0 : expm1f(o0);
        r.y = (o1 > 0.f) ? o1 : expm1f(o1);
        ((float2*)sact[wid])[l] = r;
    }
    __syncthreads();

    // ---- gemm2 phase: 320 threads, each computes 2 nodes at the same f ----
    if (t < 320) {
        const int f  = t % OUTC;
        const int g2 = t / OUTC;                 // 0..7 -> nodes 2g2, 2g2+1
        const int n0 = 2 * g2, n1 = 2 * g2 + 1;
        const float4* a0 = (const float4*)(sact[n0]);
        const float4* a1 = (const float4*)(sact[n1]);
        float acc0 = 0.f, acc1 = 0.f;
        #pragma unroll 4
        for (int k4 = 0; k4 < H1DIM / 4; k4++) {
            int kb = k4 * 4;
            float w0 = wT[(kb + 0) * OUTC + f];
            float w1 = wT[(kb + 1) * OUTC + f];
            float w2 = wT[(kb + 2) * OUTC + f];
            float w3 = wT[(kb + 3) * OUTC + f];
            float4 v0 = a0[k4];
            float4 v1 = a1[k4];
            acc0 += v0.x*w0 + v0.y*w1 + v0.z*w2 + v0.w*w3;
            acc1 += v1.x*w0 + v1.y*w1 + v1.z*w2 + v1.w*w3;
        }
        g_h2h[(nb + n0) * OUTC + f] = __float2half(acc0);
        g_h2h[(nb + n1) * OUTC + f] = __float2half(acc1);
        float asf = as_w[f], adf = ad_w[f];
        ps[n0 * OUTC + f] = acc0 * asf;
        ps[n1 * OUTC + f] = acc1 * asf;
        pd[n0 * OUTC + f] = acc0 * adf;
        pd[n1 * OUTC + f] = acc1 * adf;
    }
    __syncthreads();

    if (t < 32) {
        int node = t & 15;
        const float* p = (t < 16) ? (ps + node * OUTC) : (pd + node * OUTC);
        float ss = 0.f;
        #pragma unroll
        for (int i = 0; i < OUTC; i++) ss += p[i];
        if (t < 16) g_as2[nb + node] = ss;
        else        g_ad2[nb + node] = ss;
    }
}

// ---- layer-2 aggregation: warp/node, half2 lanes (l<20) ----
__global__ void __launch_bounds__(256, 5) k_agg2(const float* __restrict__ b2,
                                                 float* __restrict__ out) {
    const int n = blockIdx.x * 8 + (threadIdx.x >> 5);
    const int l = threadIdx.x & 31;
    const int start = g_rowptr[n], end = g_rowptr[n + 1];
    const float ad = __ldg(&g_ad2[n]);
    const __half2* __restrict__ H = (const __half2*)g_h2h;
    const bool act = (l < 20);
    const float2 zz = make_float2(0.f, 0.f);

    float accx = 0.f, accy = 0.f, den = 0.f;
    for (int eb = start; eb < end; eb += 32) {
        int m = end - eb; if (m > 32) m = 32;
        int s = 0; float ex = 0.f;
        if (l < m) {
            s = __ldg(&g_csr_src[eb + l]);
            float v = __ldg(&g_as2[s]) + ad;
            v = (v > 0.f) ? v : 0.2f * v;
            ex = __expf(v);
        }
        den += ex;
        #pragma unroll
        for (int j = 0; j < 32; j += 4) {
            if (j >= m) break;
            int   s0 = __shfl_sync(FULL, s,  j + 0);
            int   s1 = __shfl_sync(FULL, s,  j + 1);
            int   s2 = __shfl_sync(FULL, s,  j + 2);
            int   s3 = __shfl_sync(FULL, s,  j + 3);
            float x0 = __shfl_sync(FULL, ex, j + 0);
            float x1 = __shfl_sync(FULL, ex, j + 1);
            float x2 = __shfl_sync(FULL, ex, j + 2);
            float x3 = __shfl_sync(FULL, ex, j + 3);
            float2 r0 = act ? __half22float2(__ldg(&H[s0 * 20 + l])) : zz;
            float2 r1 = act ? __half22float2(__ldg(&H[s1 * 20 + l])) : zz;
            float2 r2 = act ? __half22float2(__ldg(&H[s2 * 20 + l])) : zz;
            float2 r3 = act ? __half22float2(__ldg(&H[s3 * 20 + l])) : zz;
            accx += x0 * r0.x + x1 * r1.x + x2 * r2.x + x3 * r3.x;
            accy += x0 * r0.y + x1 * r1.y + x2 * r2.y + x3 * r3.y;
        }
    }
    #pragma unroll
    for (int off = 1; off < 32; off <<= 1) den += __shfl_xor_sync(FULL, den, off);

    if (act) {
        float2 bb = __ldg(&((const float2*)b2)[l]);
        float2 r;
        r.x = accx / den + bb.x;
        r.y = accy / den + bb.y;
        ((float2*)out)[n * 20 + l] = r;
    }
}

extern "C" void kernel_launch(void* const* d_in, const int* in_sizes, int n_in,
                              void* d_out, int out_size) {
    const float* x   = (const float*)d_in[0];
    const int*   ei  = (const int*)  d_in[1];
    const float* W1  = (const float*)d_in[2];
    const float* as1 = (const float*)d_in[3];
    const float* ad1 = (const float*)d_in[4];
    const float* b1  = (const float*)d_in[5];
    const float* W2  = (const float*)d_in[6];
    const float* as2 = (const float*)d_in[7];
    const float* ad2 = (const float*)d_in[8];
    const float* b2  = (const float*)d_in[9];
    float* out = (float*)d_out;

    int nE = in_sizes[1] / 2;
    const int* src = ei;
    const int* dst = ei + nE;

    const int T = 256;
    int eg = (nE + T - 1) / T;

    static cudaStream_t s2 = nullptr;
    static cudaEvent_t evFork = nullptr, evJoin = nullptr;
    static int* cnt_addr = nullptr;
    static int* cur_addr = nullptr;
    if (s2 == nullptr) {
        cudaStreamCreateWithFlags(&s2, cudaStreamNonBlocking);
        cudaEventCreateWithFlags(&evFork, cudaEventDisableTiming);
        cudaEventCreateWithFlags(&evJoin, cudaEventDisableTiming);
        cudaGetSymbolAddress((void**)&cnt_addr, g_cnt);
        cudaGetSymbolAddress((void**)&cur_addr, g_cur);
    }

    // fork first; gemm1 submitted (and recorded) BEFORE any wait on evJoin
    cudaEventRecord(evFork, 0);
    cudaStreamWaitEvent(s2, evFork, 0);
    k_gemm1<<<NN / 16, 256, 0, s2>>>(x, W1, as1, ad1);   // launch #1 (s2)
    cudaEventRecord(evJoin, s2);

    // main stream: CSR build
    cudaMemsetAsync(cnt_addr, 0, NN * sizeof(int), 0);
    cudaMemsetAsync(cur_addr, 0, NN * sizeof(int), 0);
    k_hist    <<<eg, T>>>(dst, nE);            // launch #2
    k_scanfill<<<SCANB, 1024>>>(src, dst, nE); // launch #3

    // join: agg1g2 needs gemm1 results
    cudaStreamWaitEvent(0, evJoin, 0);
    k_agg1g2<<<NN / 16, 512>>>(b1, W2, as2, ad2);  // launch #4 -> ncu capture
    k_agg2  <<<NN / 8, 256>>>(b2, out);            // launch #5
}